// round 3
// baseline (speedup 1.0000x reference)
#include <cuda_runtime.h>
#include <math.h>

// Problem dims (fixed by the reference)
#define BB 8
#define NN 2048
#define DD 1024

// Scratch (allocation-free rule: __device__ globals)
__device__ float g_Q[(size_t)BB * NN * DD];
__device__ float g_K[(size_t)BB * NN * DD];
__device__ float g_V[(size_t)BB * NN * DD];
__device__ float g_S[(size_t)BB * NN * NN];

// ---------------------------------------------------------------------------
// Tiled SGEMM helpers: BM=BN=128, BK=8, 256 threads, 8x8 per-thread microtile.
// NT: C[m,n] = alpha * sum_k A[m,k] * B[n,k]   (both K-contiguous)
// NN: C[m,n] = alpha * sum_k A[m,k] * B[k,n]   (A K-contig, B N-contig)
// All dims assumed multiples of the tile sizes (true here).
// ---------------------------------------------------------------------------

__device__ __forceinline__ void sgemm_nt_tile(
    const float* __restrict__ A,   // [*, K] rows at bm*128
    const float* __restrict__ B,   // [*, K] rows at bn*128
    float* __restrict__ C,         // [*, ldc]
    int ldc, int K, int bm, int bn, float alpha)
{
    __shared__ float As[8][128];
    __shared__ float Bs[8][128];

    const int tid   = threadIdx.x;          // 0..255
    const int lrow  = tid >> 1;             // 0..127
    const int lk4   = (tid & 1) * 4;        // 0 or 4
    const int trow  = tid >> 4;             // 0..15
    const int tcol  = tid & 15;             // 0..15

    const float* Aptr = A + (size_t)(bm * 128 + lrow) * K + lk4;
    const float* Bptr = B + (size_t)(bn * 128 + lrow) * K + lk4;

    float acc[8][8];
#pragma unroll
    for (int i = 0; i < 8; i++)
#pragma unroll
        for (int j = 0; j < 8; j++) acc[i][j] = 0.f;

    float4 av = *(const float4*)(Aptr);
    float4 bv = *(const float4*)(Bptr);

    for (int k0 = 0; k0 < K; k0 += 8) {
        As[lk4 + 0][lrow] = av.x;
        As[lk4 + 1][lrow] = av.y;
        As[lk4 + 2][lrow] = av.z;
        As[lk4 + 3][lrow] = av.w;
        Bs[lk4 + 0][lrow] = bv.x;
        Bs[lk4 + 1][lrow] = bv.y;
        Bs[lk4 + 2][lrow] = bv.z;
        Bs[lk4 + 3][lrow] = bv.w;
        __syncthreads();

        if (k0 + 8 < K) {
            av = *(const float4*)(Aptr + k0 + 8);
            bv = *(const float4*)(Bptr + k0 + 8);
        }

#pragma unroll
        for (int kk = 0; kk < 8; kk++) {
            float4 a0 = *(const float4*)&As[kk][trow * 8];
            float4 a1 = *(const float4*)&As[kk][trow * 8 + 4];
            float4 b0 = *(const float4*)&Bs[kk][tcol * 8];
            float4 b1 = *(const float4*)&Bs[kk][tcol * 8 + 4];
            float ra[8] = {a0.x, a0.y, a0.z, a0.w, a1.x, a1.y, a1.z, a1.w};
            float rb[8] = {b0.x, b0.y, b0.z, b0.w, b1.x, b1.y, b1.z, b1.w};
#pragma unroll
            for (int i = 0; i < 8; i++)
#pragma unroll
                for (int j = 0; j < 8; j++)
                    acc[i][j] += ra[i] * rb[j];
        }
        __syncthreads();
    }

#pragma unroll
    for (int i = 0; i < 8; i++) {
        size_t base = (size_t)(bm * 128 + trow * 8 + i) * ldc + bn * 128 + tcol * 8;
        float4 c0, c1;
        c0.x = acc[i][0] * alpha; c0.y = acc[i][1] * alpha;
        c0.z = acc[i][2] * alpha; c0.w = acc[i][3] * alpha;
        c1.x = acc[i][4] * alpha; c1.y = acc[i][5] * alpha;
        c1.z = acc[i][6] * alpha; c1.w = acc[i][7] * alpha;
        *(float4*)&C[base]     = c0;
        *(float4*)&C[base + 4] = c1;
    }
}

__device__ __forceinline__ void sgemm_nn_tile(
    const float* __restrict__ A,   // [*, K] K-contig
    const float* __restrict__ B,   // [K, ldb] N-contig
    float* __restrict__ C,         // [*, ldc]
    int ldb, int ldc, int Kmax, int bm, int bn, float alpha)
{
    __shared__ float As[8][128];
    __shared__ float Bs[8][128];

    const int tid   = threadIdx.x;
    const int lrow  = tid >> 1;             // A: 0..127
    const int lk4   = (tid & 1) * 4;
    const int brow  = tid >> 5;             // B: 0..7
    const int bc4   = (tid & 31) * 4;       // B: 0..124
    const int trow  = tid >> 4;
    const int tcol  = tid & 15;

    // K for A's row stride equals the full S width (NN), Kmax only limits loop.
    const int lda = NN;
    const float* Aptr = A + (size_t)(bm * 128 + lrow) * lda + lk4;
    const float* Bptr = B + (size_t)brow * ldb + bn * 128 + bc4;

    float acc[8][8];
#pragma unroll
    for (int i = 0; i < 8; i++)
#pragma unroll
        for (int j = 0; j < 8; j++) acc[i][j] = 0.f;

    float4 av = *(const float4*)(Aptr);
    float4 bv = *(const float4*)(Bptr);

    for (int k0 = 0; k0 < Kmax; k0 += 8) {
        As[lk4 + 0][lrow] = av.x;
        As[lk4 + 1][lrow] = av.y;
        As[lk4 + 2][lrow] = av.z;
        As[lk4 + 3][lrow] = av.w;
        *(float4*)&Bs[brow][bc4] = bv;
        __syncthreads();

        if (k0 + 8 < Kmax) {
            av = *(const float4*)(Aptr + k0 + 8);
            bv = *(const float4*)(Bptr + (size_t)(k0 + 8) * ldb);
        }

#pragma unroll
        for (int kk = 0; kk < 8; kk++) {
            float4 a0 = *(const float4*)&As[kk][trow * 8];
            float4 a1 = *(const float4*)&As[kk][trow * 8 + 4];
            float4 b0 = *(const float4*)&Bs[kk][tcol * 8];
            float4 b1 = *(const float4*)&Bs[kk][tcol * 8 + 4];
            float ra[8] = {a0.x, a0.y, a0.z, a0.w, a1.x, a1.y, a1.z, a1.w};
            float rb[8] = {b0.x, b0.y, b0.z, b0.w, b1.x, b1.y, b1.z, b1.w};
#pragma unroll
            for (int i = 0; i < 8; i++)
#pragma unroll
                for (int j = 0; j < 8; j++)
                    acc[i][j] += ra[i] * rb[j];
        }
        __syncthreads();
    }

#pragma unroll
    for (int i = 0; i < 8; i++) {
        size_t base = (size_t)(bm * 128 + trow * 8 + i) * ldc + bn * 128 + tcol * 8;
        float4 c0, c1;
        c0.x = acc[i][0] * alpha; c0.y = acc[i][1] * alpha;
        c0.z = acc[i][2] * alpha; c0.w = acc[i][3] * alpha;
        c1.x = acc[i][4] * alpha; c1.y = acc[i][5] * alpha;
        c1.z = acc[i][6] * alpha; c1.w = acc[i][7] * alpha;
        *(float4*)&C[base]     = c0;
        *(float4*)&C[base + 4] = c1;
    }
}

// ---------------------------------------------------------------------------
// Kernel 1: Q/K/V projections. grid = (DD/128, B*NN/128, 3)
//   C[m, n] = sum_d x[m, d] * W[n, d]   (NT gemm, M = B*NN folded)
// ---------------------------------------------------------------------------
__global__ __launch_bounds__(256)
void qkv_kernel(const float* __restrict__ x,
                const float* __restrict__ Wq,
                const float* __restrict__ Wk,
                const float* __restrict__ Wv)
{
    const int z = blockIdx.z;
    const float* W = (z == 0) ? Wq : (z == 1) ? Wk : Wv;
    float* C = (z == 0) ? g_Q : (z == 1) ? g_K : g_V;
    sgemm_nt_tile(x, W, C, DD, DD, blockIdx.y, blockIdx.x, 1.0f);
}

// ---------------------------------------------------------------------------
// Kernel 2: S = (Q K^T) / sqrt(DK), lower-triangular blocks only.
// grid = (NN/128, NN/128, B); blocks with bn > bm exit (never read by softmax).
// ---------------------------------------------------------------------------
__global__ __launch_bounds__(256)
void scores_kernel()
{
    const int bn = blockIdx.x, bm = blockIdx.y, b = blockIdx.z;
    if (bn > bm) return;
    const float* Q = g_Q + (size_t)b * NN * DD;
    const float* K = g_K + (size_t)b * NN * DD;
    float* S = g_S + (size_t)b * NN * NN;
    sgemm_nt_tile(Q, K, S, NN, DD, bm, bn, 0.03125f);  // 1/sqrt(1024)
}

// ---------------------------------------------------------------------------
// Kernel 3: causal row softmax. grid = (NN, B), 256 threads.
// Row i uses cols [0, i]; zero-fills [i+1, roundup128(i+1)) so the NN gemm can
// read whole 128-wide K blocks.
// ---------------------------------------------------------------------------
__global__ __launch_bounds__(256)
void softmax_kernel()
{
    const int i = blockIdx.x, b = blockIdx.y;
    float* row = g_S + ((size_t)b * NN + i) * NN;
    const int len = i + 1;
    const int t = threadIdx.x;

    float vals[8];
    float m = -INFINITY;
#pragma unroll
    for (int k = 0; k < 8; k++) {
        int j = t + k * 256;
        float s = (j < len) ? row[j] : -INFINITY;
        vals[k] = s;
        m = fmaxf(m, s);
    }

    __shared__ float red[256];
    red[t] = m;
    __syncthreads();
    for (int s = 128; s > 0; s >>= 1) {
        if (t < s) red[t] = fmaxf(red[t], red[t + s]);
        __syncthreads();
    }
    m = red[0];
    __syncthreads();

    float sum = 0.f;
#pragma unroll
    for (int k = 0; k < 8; k++) {
        int j = t + k * 256;
        if (j < len) {
            vals[k] = expf(vals[k] - m);
            sum += vals[k];
        } else {
            vals[k] = 0.f;
        }
    }
    red[t] = sum;
    __syncthreads();
    for (int s = 128; s > 0; s >>= 1) {
        if (t < s) red[t] += red[t + s];
        __syncthreads();
    }
    const float inv = 1.0f / red[0];

    const int cap = (len + 127) & ~127;
#pragma unroll
    for (int k = 0; k < 8; k++) {
        int j = t + k * 256;
        if (j < cap) row[j] = vals[k] * inv;
    }
}

// ---------------------------------------------------------------------------
// Kernel 4: O = P V. grid = (DD/128, NN/128, B). NN gemm, K truncated by
// causality to (bm+1)*128.
// ---------------------------------------------------------------------------
__global__ __launch_bounds__(256)
void out_kernel(float* __restrict__ out)
{
    const int bn = blockIdx.x, bm = blockIdx.y, b = blockIdx.z;
    const float* P = g_S + (size_t)b * NN * NN;
    const float* V = g_V + (size_t)b * NN * DD;
    float* C = out + (size_t)b * NN * DD;
    const int Kmax = (bm + 1) * 128;
    sgemm_nn_tile(P, V, C, DD, DD, Kmax, bm, bn, 1.0f);
}

// ---------------------------------------------------------------------------
extern "C" void kernel_launch(void* const* d_in, const int* in_sizes, int n_in,
                              void* d_out, int out_size)
{
    const float* x  = (const float*)d_in[0];
    const float* Wq = (const float*)d_in[1];
    const float* Wk = (const float*)d_in[2];
    const float* Wv = (const float*)d_in[3];
    float* out = (float*)d_out;

    dim3 qkvGrid(DD / 128, (BB * NN) / 128, 3);       // (8, 128, 3)
    qkv_kernel<<<qkvGrid, 256>>>(x, Wq, Wk, Wv);

    dim3 sGrid(NN / 128, NN / 128, BB);               // (16, 16, 8)
    scores_kernel<<<sGrid, 256>>>();

    dim3 smGrid(NN, BB);                              // (2048, 8)
    softmax_kernel<<<smGrid, 256>>>();

    dim3 oGrid(DD / 128, NN / 128, BB);               // (8, 16, 8)
    out_kernel<<<oGrid, 256>>>(out);
}

// round 6
// speedup vs baseline: 2.6924x; 2.6924x over previous
#include <cuda_runtime.h>
#include <cuda_bf16.h>
#include <stdint.h>
#include <math.h>

// Fixed problem dims
#define NB   8
#define SEQB 2048
#define DIMQ 1024

static constexpr size_t XE = (size_t)NB * SEQB * DIMQ;   // 16,777,216
static constexpr size_t WE = (size_t)DIMQ * DIMQ;        // 1,048,576
static constexpr size_t SE = (size_t)NB * SEQB * SEQB;   // 33,554,432

// Scratch (__device__ globals: allocation-free rule)
__device__ __nv_bfloat16 g_xhi[XE],  g_xlo[XE];
__device__ __nv_bfloat16 g_wqhi[WE], g_wqlo[WE];
__device__ __nv_bfloat16 g_wkhi[WE], g_wklo[WE];
__device__ __nv_bfloat16 g_wvhi[WE], g_wvlo[WE];
__device__ __nv_bfloat16 g_Qhi[XE],  g_Qlo[XE];
__device__ __nv_bfloat16 g_Khi[XE],  g_Klo[XE];
__device__ __nv_bfloat16 g_Vthi[XE], g_Vtlo[XE];
__device__ float         g_S[SE];
__device__ __nv_bfloat16 g_Phi[SE],  g_Plo[SE];

// ---------------------------------------------------------------------------
// PTX helpers (baseline PTX only — no 'a'-gated features)
// ---------------------------------------------------------------------------
__device__ __forceinline__ uint32_t smem_u32(const void* p) {
    uint32_t a;
    asm("{ .reg .u64 t; cvta.to.shared.u64 t, %1; cvt.u32.u64 %0, t; }"
        : "=r"(a) : "l"(p));
    return a;
}

__device__ __forceinline__ void ldsm_x4(uint32_t addr, uint32_t& r0, uint32_t& r1,
                                        uint32_t& r2, uint32_t& r3) {
    asm volatile("ldmatrix.sync.aligned.m8n8.x4.shared.b16 {%0,%1,%2,%3}, [%4];"
                 : "=r"(r0), "=r"(r1), "=r"(r2), "=r"(r3) : "r"(addr));
}

__device__ __forceinline__ void mma16816(float& d0, float& d1, float& d2, float& d3,
                                         uint32_t a0, uint32_t a1, uint32_t a2, uint32_t a3,
                                         uint32_t b0, uint32_t b1) {
    asm volatile(
        "mma.sync.aligned.m16n8k16.row.col.f32.bf16.bf16.f32 "
        "{%0,%1,%2,%3}, {%4,%5,%6,%7}, {%8,%9}, {%0,%1,%2,%3};"
        : "+f"(d0), "+f"(d1), "+f"(d2), "+f"(d3)
        : "r"(a0), "r"(a1), "r"(a2), "r"(a3), "r"(b0), "r"(b1));
}

// ---------------------------------------------------------------------------
// GEMM-NT core: C[128,128] tile at (m0,n0) = sum_k A[m,k]*B[n,k], K = kb*64,
// as AhiBhi + AloBhi + AhiBlo (3 K-passes, fp32 accum in registers).
// mode 0: write fp32*alpha; mode 1: write split hi/lo bf16.
// 256 threads = 8 warps (2m x 4n), warp tile 64x32, BK=64 bf16, SW128 smem.
// ---------------------------------------------------------------------------
#define STAGES  3
#define STAGE_B 16384
#define SMEM_SZ (2 * STAGES * STAGE_B)   // 98304

__device__ __forceinline__ void gemm128_nt(
    const __nv_bfloat16* __restrict__ Ahi, const __nv_bfloat16* __restrict__ Alo,
    const __nv_bfloat16* __restrict__ Bhi, const __nv_bfloat16* __restrict__ Blo,
    int lda, int ldb, int kb, int m0, int n0, int ldc,
    float* __restrict__ C32,
    __nv_bfloat16* __restrict__ Chi, __nv_bfloat16* __restrict__ Clo,
    float alpha, int mode)
{
    extern __shared__ char smem[];
    const uint32_t sbase = smem_u32(smem);
    const int tid  = threadIdx.x;
    const int wid  = tid >> 5;
    const int lane = tid & 31;
    const int wm = wid >> 2;      // 0..1
    const int wn = wid & 3;       // 0..3

    const int nc = 3 * kb;

    auto load_chunk = [&](int c, int s) {
        int p  = (c >= kb) + (c >= 2 * kb);
        int k0 = (c - p * kb) * 64;
        const __nv_bfloat16* As = (p == 1) ? Alo : Ahi;
        const __nv_bfloat16* Bs = (p == 2) ? Blo : Bhi;
        uint32_t aS = sbase + s * STAGE_B;
        uint32_t bS = sbase + STAGES * STAGE_B + s * STAGE_B;
#pragma unroll
        for (int i = 0; i < 4; i++) {
            int o = tid + i * 256;            // 0..1023 : 128 rows x 8 x 16B
            int row = o >> 3, seg = o & 7;
            uint32_t off = (uint32_t)(o << 4);
            uint32_t sw = off ^ ((off >> 3) & 0x70);
            const __nv_bfloat16* ga = As + (size_t)(m0 + row) * lda + k0 + seg * 8;
            const __nv_bfloat16* gb = Bs + (size_t)(n0 + row) * ldb + k0 + seg * 8;
            asm volatile("cp.async.cg.shared.global [%0], [%1], 16;" :: "r"(aS + sw), "l"(ga));
            asm volatile("cp.async.cg.shared.global [%0], [%1], 16;" :: "r"(bS + sw), "l"(gb));
        }
        asm volatile("cp.async.commit_group;" ::: "memory");
    };

    float acc[4][4][4];
#pragma unroll
    for (int i = 0; i < 4; i++)
#pragma unroll
        for (int j = 0; j < 4; j++)
#pragma unroll
            for (int k = 0; k < 4; k++) acc[i][j][k] = 0.f;

    // Prologue: 2 chunks in flight (nc >= 6 always here)
    load_chunk(0, 0);
    load_chunk(1, 1);

    const int lrow = lane & 15;
    const int lhi  = (lane >> 4) & 1;

    for (int c = 0; c < nc; c++) {
        const int s = c % STAGES;
        asm volatile("cp.async.wait_group 1;" ::: "memory");   // chunk c resident
        __syncthreads();

        const int nxt = c + 2;
        if (nxt < nc) load_chunk(nxt, nxt % STAGES);
        else asm volatile("cp.async.commit_group;" ::: "memory");  // keep counts uniform

        const uint32_t aS = sbase + s * STAGE_B;
        const uint32_t bS = sbase + STAGES * STAGE_B + s * STAGE_B;
#pragma unroll
        for (int kk = 0; kk < 4; kk++) {
            uint32_t a[4][4], b[2][4];
            const uint32_t col = (uint32_t)(kk * 32 + lhi * 16);
#pragma unroll
            for (int mf = 0; mf < 4; mf++) {
                int row = wm * 64 + mf * 16 + lrow;
                uint32_t addr = aS + row * 128 + (col ^ ((row & 7) << 4));
                ldsm_x4(addr, a[mf][0], a[mf][1], a[mf][2], a[mf][3]);
            }
#pragma unroll
            for (int nf2 = 0; nf2 < 2; nf2++) {
                int row = wn * 32 + nf2 * 16 + lrow;
                uint32_t addr = bS + row * 128 + (col ^ ((row & 7) << 4));
                ldsm_x4(addr, b[nf2][0], b[nf2][1], b[nf2][2], b[nf2][3]);
            }
#pragma unroll
            for (int mf = 0; mf < 4; mf++)
#pragma unroll
                for (int nf = 0; nf < 4; nf++) {
                    uint32_t bb0 = (nf & 1) ? b[nf >> 1][1] : b[nf >> 1][0];
                    uint32_t bb1 = (nf & 1) ? b[nf >> 1][3] : b[nf >> 1][2];
                    mma16816(acc[mf][nf][0], acc[mf][nf][1], acc[mf][nf][2], acc[mf][nf][3],
                             a[mf][0], a[mf][1], a[mf][2], a[mf][3], bb0, bb1);
                }
        }
    }

    // Epilogue: straight from registers.
#pragma unroll
    for (int mf = 0; mf < 4; mf++) {
#pragma unroll
        for (int nf = 0; nf < 4; nf++) {
            const int r0  = m0 + wm * 64 + mf * 16 + (lane >> 2);
            const int col = n0 + wn * 32 + nf * 8 + (lane & 3) * 2;
            float d0 = acc[mf][nf][0], d1 = acc[mf][nf][1];
            float d2 = acc[mf][nf][2], d3 = acc[mf][nf][3];
            if (mode == 0) {
                float2 u, v;
                u.x = d0 * alpha; u.y = d1 * alpha;
                v.x = d2 * alpha; v.y = d3 * alpha;
                *(float2*)(C32 + (size_t)r0 * ldc + col)       = u;
                *(float2*)(C32 + (size_t)(r0 + 8) * ldc + col) = v;
            } else {
                float f[4] = {d0, d1, d2, d3};
                unsigned short hs[4], ls[4];
#pragma unroll
                for (int k = 0; k < 4; k++) {
                    __nv_bfloat16 h = __float2bfloat16(f[k]);
                    __nv_bfloat16 l = __float2bfloat16(f[k] - __bfloat162float(h));
                    hs[k] = __bfloat16_as_ushort(h);
                    ls[k] = __bfloat16_as_ushort(l);
                }
                *(uint32_t*)(Chi + (size_t)r0 * ldc + col)       = hs[0] | ((uint32_t)hs[1] << 16);
                *(uint32_t*)(Chi + (size_t)(r0 + 8) * ldc + col) = hs[2] | ((uint32_t)hs[3] << 16);
                *(uint32_t*)(Clo + (size_t)r0 * ldc + col)       = ls[0] | ((uint32_t)ls[1] << 16);
                *(uint32_t*)(Clo + (size_t)(r0 + 8) * ldc + col) = ls[2] | ((uint32_t)ls[3] << 16);
            }
        }
    }
}

// ---------------------------------------------------------------------------
// Conversion kernels: fp32 -> bf16 hi/lo split
// ---------------------------------------------------------------------------
__device__ __forceinline__ void split4_store(float4 v, __nv_bfloat16* dh, __nv_bfloat16* dl, size_t i) {
    float f[4] = {v.x, v.y, v.z, v.w};
    unsigned short hs[4], ls[4];
#pragma unroll
    for (int k = 0; k < 4; k++) {
        __nv_bfloat16 h = __float2bfloat16(f[k]);
        __nv_bfloat16 l = __float2bfloat16(f[k] - __bfloat162float(h));
        hs[k] = __bfloat16_as_ushort(h);
        ls[k] = __bfloat16_as_ushort(l);
    }
    *(uint2*)(dh + i) = make_uint2(hs[0] | ((uint32_t)hs[1] << 16), hs[2] | ((uint32_t)hs[3] << 16));
    *(uint2*)(dl + i) = make_uint2(ls[0] | ((uint32_t)ls[1] << 16), ls[2] | ((uint32_t)ls[3] << 16));
}

__global__ __launch_bounds__(256) void k_conv_x(const float* __restrict__ x) {
    size_t i = ((size_t)blockIdx.x * 256 + threadIdx.x) * 4;
    split4_store(*(const float4*)(x + i), g_xhi, g_xlo, i);
}

__global__ __launch_bounds__(256) void k_conv_w(const float* __restrict__ Wq,
                                                const float* __restrict__ Wk,
                                                const float* __restrict__ Wv) {
    const int z = blockIdx.z;
    const float* src = (z == 0) ? Wq : (z == 1) ? Wk : Wv;
    __nv_bfloat16* dh = (z == 0) ? g_wqhi : (z == 1) ? g_wkhi : g_wvhi;
    __nv_bfloat16* dl = (z == 0) ? g_wqlo : (z == 1) ? g_wklo : g_wvlo;
    size_t i = ((size_t)blockIdx.x * 256 + threadIdx.x) * 4;
    split4_store(*(const float4*)(src + i), dh, dl, i);
}

// ---------------------------------------------------------------------------
// GEMM wrappers
// ---------------------------------------------------------------------------
__global__ __launch_bounds__(256, 2) void k_proj_qk() {
    const int z = blockIdx.z;
    const __nv_bfloat16* bh = z ? g_wkhi : g_wqhi;
    const __nv_bfloat16* bl = z ? g_wklo : g_wqlo;
    __nv_bfloat16* ch = z ? g_Khi : g_Qhi;
    __nv_bfloat16* cl = z ? g_Klo : g_Qlo;
    gemm128_nt(g_xhi, g_xlo, bh, bl, DIMQ, DIMQ, DIMQ / 64,
               blockIdx.y * 128, blockIdx.x * 128, DIMQ,
               nullptr, ch, cl, 1.f, 1);
}

__global__ __launch_bounds__(256, 2) void k_proj_vt() {
    const int b = blockIdx.z;
    gemm128_nt(g_wvhi, g_wvlo,
               g_xhi + (size_t)b * SEQB * DIMQ, g_xlo + (size_t)b * SEQB * DIMQ,
               DIMQ, DIMQ, DIMQ / 64,
               blockIdx.y * 128, blockIdx.x * 128, SEQB,
               nullptr, g_Vthi + (size_t)b * DIMQ * SEQB, g_Vtlo + (size_t)b * DIMQ * SEQB,
               1.f, 1);
}

__global__ __launch_bounds__(256, 2) void k_scores() {
    const int bn = blockIdx.x, bm = blockIdx.y, b = blockIdx.z;
    if (bn > bm) return;
    gemm128_nt(g_Qhi + (size_t)b * SEQB * DIMQ, g_Qlo + (size_t)b * SEQB * DIMQ,
               g_Khi + (size_t)b * SEQB * DIMQ, g_Klo + (size_t)b * SEQB * DIMQ,
               DIMQ, DIMQ, DIMQ / 64, bm * 128, bn * 128, SEQB,
               g_S + (size_t)b * SEQB * SEQB, nullptr, nullptr, 0.03125f, 0);
}

__global__ __launch_bounds__(256, 2) void k_out(float* __restrict__ out) {
    const int bn = blockIdx.x, bm = blockIdx.y, b = blockIdx.z;
    gemm128_nt(g_Phi + (size_t)b * SEQB * SEQB, g_Plo + (size_t)b * SEQB * SEQB,
               g_Vthi + (size_t)b * DIMQ * SEQB, g_Vtlo + (size_t)b * DIMQ * SEQB,
               SEQB, SEQB, (bm + 1) * 2, bm * 128, bn * 128, DIMQ,
               out + (size_t)b * SEQB * DIMQ, nullptr, nullptr, 1.f, 0);
}

// ---------------------------------------------------------------------------
// Causal softmax: S fp32 row -> P split hi/lo, zero-padded to 128 boundary
// ---------------------------------------------------------------------------
__global__ __launch_bounds__(256) void k_softmax() {
    const int i = blockIdx.x, b = blockIdx.y;
    const float* row = g_S + ((size_t)b * SEQB + i) * SEQB;
    __nv_bfloat16* ph = g_Phi + ((size_t)b * SEQB + i) * SEQB;
    __nv_bfloat16* pl = g_Plo + ((size_t)b * SEQB + i) * SEQB;
    const int len = i + 1;
    const int t = threadIdx.x;

    float vals[8];
    float m = -1e30f;
#pragma unroll
    for (int k = 0; k < 8; k++) {
        int j = t + k * 256;
        float s = (j < len) ? row[j] : -1e30f;
        vals[k] = s;
        m = fmaxf(m, s);
    }
    __shared__ float red[256];
    red[t] = m;
    __syncthreads();
    for (int s = 128; s > 0; s >>= 1) {
        if (t < s) red[t] = fmaxf(red[t], red[t + s]);
        __syncthreads();
    }
    m = red[0];
    __syncthreads();

    float sum = 0.f;
#pragma unroll
    for (int k = 0; k < 8; k++) {
        int j = t + k * 256;
        if (j < len) { vals[k] = expf(vals[k] - m); sum += vals[k]; }
        else vals[k] = 0.f;
    }
    red[t] = sum;
    __syncthreads();
    for (int s = 128; s > 0; s >>= 1) {
        if (t < s) red[t] += red[t + s];
        __syncthreads();
    }
    const float inv = 1.0f / red[0];

    const int cap = (len + 127) & ~127;
#pragma unroll
    for (int k = 0; k < 8; k++) {
        int j = t + k * 256;
        if (j < cap) {
            float p = vals[k] * inv;
            __nv_bfloat16 h = __float2bfloat16(p);
            __nv_bfloat16 l = __float2bfloat16(p - __bfloat162float(h));
            ph[j] = h;
            pl[j] = l;
        }
    }
}

// ---------------------------------------------------------------------------
extern "C" void kernel_launch(void* const* d_in, const int* in_sizes, int n_in,
                              void* d_out, int out_size)
{
    const float* x  = (const float*)d_in[0];
    const float* Wq = (const float*)d_in[1];
    const float* Wk = (const float*)d_in[2];
    const float* Wv = (const float*)d_in[3];
    float* out = (float*)d_out;

    cudaFuncSetAttribute(k_proj_qk, cudaFuncAttributeMaxDynamicSharedMemorySize, SMEM_SZ);
    cudaFuncSetAttribute(k_proj_vt, cudaFuncAttributeMaxDynamicSharedMemorySize, SMEM_SZ);
    cudaFuncSetAttribute(k_scores,  cudaFuncAttributeMaxDynamicSharedMemorySize, SMEM_SZ);
    cudaFuncSetAttribute(k_out,     cudaFuncAttributeMaxDynamicSharedMemorySize, SMEM_SZ);

    k_conv_x<<<(unsigned)(XE / 1024), 256>>>(x);
    k_conv_w<<<dim3((unsigned)(WE / 1024), 1, 3), 256>>>(Wq, Wk, Wv);

    k_proj_qk<<<dim3(DIMQ / 128, (NB * SEQB) / 128, 2), 256, SMEM_SZ>>>();   // (8,128,2)
    k_proj_vt<<<dim3(SEQB / 128, DIMQ / 128, NB), 256, SMEM_SZ>>>();         // (16,8,8)
    k_scores <<<dim3(SEQB / 128, SEQB / 128, NB), 256, SMEM_SZ>>>();         // (16,16,8)
    k_softmax<<<dim3(SEQB, NB), 256>>>();                                    // (2048,8)
    k_out    <<<dim3(DIMQ / 128, SEQB / 128, NB), 256, SMEM_SZ>>>(out);      // (8,16,8)
}